// round 5
// baseline (speedup 1.0000x reference)
#include <cuda_runtime.h>

#define HASH_SIZE 10240
#define PROJ_DIM  128
#define MODEL_DIM 512
#define NBATCH    8
#define SEQ       8192

// Fused table: fused[h][m] = scale * sum_k embed[h][k] * proj[m][k]  (21 MB)
__device__ float g_fused[HASH_SIZE * MODEL_DIM];

// ---------------------------------------------------------------------------
// Kernel 1: build the fused table. C = scale * E (10240x128) @ P (512x128)^T
// Tile BM=128, BN=128, BK=32, 256 threads, 8x8 micro-tile, k-vectorized
// (4 k per step via float4), quad-XOR smem swizzle.
// 320 tiles at 2 blocks/SM (296 slots) -> 1.08 waves (R4's BN=64 gave 640
// tiles -> 3-wave makespan; this removes the tail).
// Inner loop keeps ONE a-frag live (b[8] hoisted) -> ~112 live regs < 128 cap.
// ---------------------------------------------------------------------------
#define GBM 128
#define GBN 128
#define GBK 32   // 8 float4 quads per row

__device__ __forceinline__ int sw_idx(int row, int q) {
    return row * GBK + ((q ^ ((row >> 2) & 7)) << 2);
}

__global__ __launch_bounds__(256, 2) void build_table_kernel(
    const float* __restrict__ E,
    const float* __restrict__ P,
    const float* __restrict__ scale_p)
{
    __shared__ float As[GBM * GBK];   // [m][k-quad swizzled]  16 KB
    __shared__ float Bs[GBN * GBK];   // [n][k-quad swizzled]  16 KB

    const int tid = threadIdx.x;
    const int mt  = tid & 15;         // m rows: mt*4+i and 64+mt*4+i
    const int nt  = tid >> 4;         // n rows: nt*4+j and 64+nt*4+j
    const int m0  = blockIdx.x * GBM;
    const int n0  = blockIdx.y * GBN;

    const int lrow = tid >> 3;        // 0..31 (tile-load row within pass)
    const int lkq  = tid & 7;         // 0..7  (k-quad)

    float acc[8][8];
    #pragma unroll
    for (int i = 0; i < 8; i++)
        #pragma unroll
        for (int j = 0; j < 8; j++) acc[i][j] = 0.0f;

    const int msw = mt & 7;
    const int nsw = nt & 7;

    for (int k0 = 0; k0 < PROJ_DIM; k0 += GBK) {
        #pragma unroll
        for (int r = 0; r < 4; r++) {
            const int row = lrow + r * 32;
            float4 va = *(const float4*)&E[(size_t)(m0 + row) * PROJ_DIM + k0 + lkq * 4];
            *(float4*)&As[sw_idx(row, lkq)] = va;
            float4 vb = *(const float4*)&P[(size_t)(n0 + row) * PROJ_DIM + k0 + lkq * 4];
            *(float4*)&Bs[sw_idx(row, lkq)] = vb;
        }
        __syncthreads();

        #pragma unroll
        for (int kq = 0; kq < GBK / 4; kq++) {
            const int koff = (kq ^ nsw) << 2;   // nsw == msw only if nt&7==mt&7; keep separate
            float4 b[8];
            #pragma unroll
            for (int j = 0; j < 4; j++) {
                b[j]     = *(const float4*)&Bs[(nt * 4 + j)      * GBK + koff];
                b[j + 4] = *(const float4*)&Bs[(64 + nt * 4 + j) * GBK + koff];
            }
            const int koffa = (kq ^ msw) << 2;
            #pragma unroll
            for (int i = 0; i < 8; i++) {
                const int arow = (i < 4) ? (mt * 4 + i) : (64 + mt * 4 + i - 4);
                float4 a = *(const float4*)&As[arow * GBK + koffa];
                #pragma unroll
                for (int j = 0; j < 8; j++) {
                    acc[i][j] = fmaf(a.x, b[j].x, acc[i][j]);
                    acc[i][j] = fmaf(a.y, b[j].y, acc[i][j]);
                    acc[i][j] = fmaf(a.z, b[j].z, acc[i][j]);
                    acc[i][j] = fmaf(a.w, b[j].w, acc[i][j]);
                }
            }
        }
        __syncthreads();
    }

    const float s = *scale_p;
    #pragma unroll
    for (int i = 0; i < 8; i++) {
        const int m = m0 + ((i < 4) ? (mt * 4 + i) : (64 + mt * 4 + i - 4));
        float* dst = &g_fused[(size_t)m * MODEL_DIM + n0];
        float4 v0 = make_float4(acc[i][0] * s, acc[i][1] * s, acc[i][2] * s, acc[i][3] * s);
        float4 v1 = make_float4(acc[i][4] * s, acc[i][5] * s, acc[i][6] * s, acc[i][7] * s);
        *(float4*)&dst[nt * 4]      = v0;
        *(float4*)&dst[64 + nt * 4] = v1;
    }
}

// ---------------------------------------------------------------------------
// Kernel 2: hash + gather + stream out (unchanged from R4: near write floor).
// ---------------------------------------------------------------------------
__device__ __forceinline__ int hash_at(const int* __restrict__ tok, int t) {
    const int s = t & (SEQ - 1);
    if (s == 0) return HASH_SIZE - 1;
    const int t1 = __ldg(tok + t);
    const int t0 = __ldg(tok + t - 1);
    // products < 2^31: no wrap; matches jnp.mod exactly
    return ((36313 * t1) ^ (27191 * t0)) % (HASH_SIZE - 1);
}

__global__ __launch_bounds__(256) void gather_kernel(
    const int* __restrict__ tok,
    float* __restrict__ out)
{
    const int warp = (blockIdx.x * 256 + threadIdx.x) >> 5;
    const int lane = threadIdx.x & 31;
    const int tA   = warp * 2;
    const int tB   = warp * 2 + 1;

    const int hA = hash_at(tok, tA);
    const int hB = hash_at(tok, tB);

    const float4* sA = (const float4*)(g_fused + (size_t)hA * MODEL_DIM);
    const float4* sB = (const float4*)(g_fused + (size_t)hB * MODEL_DIM);
    float4* dA = (float4*)(out + (size_t)tA * MODEL_DIM);
    float4* dB = (float4*)(out + (size_t)tB * MODEL_DIM);

    float4 a0 = __ldg(sA + lane);
    float4 a1 = __ldg(sA + lane + 32);
    float4 a2 = __ldg(sA + lane + 64);
    float4 a3 = __ldg(sA + lane + 96);
    float4 b0 = __ldg(sB + lane);
    float4 b1 = __ldg(sB + lane + 32);
    float4 b2 = __ldg(sB + lane + 64);
    float4 b3 = __ldg(sB + lane + 96);

    __stcs(dA + lane,      a0);
    __stcs(dA + lane + 32, a1);
    __stcs(dA + lane + 64, a2);
    __stcs(dA + lane + 96, a3);
    __stcs(dB + lane,      b0);
    __stcs(dB + lane + 32, b1);
    __stcs(dB + lane + 64, b2);
    __stcs(dB + lane + 96, b3);
}

// ---------------------------------------------------------------------------
// Inputs (metadata order): token_ids(i32), embed_weight(f32), proj_weight(f32), scale(f32[1])
// ---------------------------------------------------------------------------
extern "C" void kernel_launch(void* const* d_in, const int* in_sizes, int n_in,
                              void* d_out, int out_size)
{
    const int*   tok   = (const int*)d_in[0];
    const float* E     = (const float*)d_in[1];
    const float* P     = (const float*)d_in[2];
    const float* scale = (const float*)d_in[3];
    float*       out   = (float*)d_out;

    dim3 gemm_grid(HASH_SIZE / GBM, MODEL_DIM / GBN);   // (80, 4) = 320 tiles
    build_table_kernel<<<gemm_grid, 256>>>(E, P, scale);

    gather_kernel<<<(NBATCH * SEQ) / 16, 256>>>(tok, out);
}

// round 9
// speedup vs baseline: 1.6092x; 1.6092x over previous
#include <cuda_runtime.h>
#include <cuda_bf16.h>
#include <cstdint>

#define HASH_SIZE 10240
#define PROJ_DIM  128
#define MODEL_DIM 512
#define NBATCH    8
#define SEQ       8192

// Fused table: fused[h][m] = scale * sum_k embed[h][k] * proj[m][k]  (21 MB)
__device__ float g_fused[HASH_SIZE * MODEL_DIM];

// ===========================================================================
// GEMM on mma.sync (bf16, m16n8k16) — sm_100-safe (no tcgen05; harness
// compiles for plain sm_100, which gates all 'a'-suffix features).
// Split-bf16: D = Ah*Bh + Ah*Bl + Al*Bh  (rel err ~1e-5).
// CTA tile: M=128, N=128, K=128 (full K). 256 threads, warp tile 32x64.
// Smem: A/B hi+lo bf16 tiles, rows of 256B (16x16B chunks),
// chunk XOR-swizzled by (row&7) -> conflict-free ldmatrix.
// ===========================================================================
#define A_HI 0
#define A_LO 32768
#define B_HI 65536
#define B_LO 98304
#define SMEM_DYN (131072 + 1024)

__device__ __forceinline__ uint32_t smem_u32(const void* p) {
    uint32_t a;
    asm("{ .reg .u64 t; cvta.to.shared.u64 t, %1; cvt.u32.u64 %0, t; }" : "=r"(a) : "l"(p));
    return a;
}

__device__ __forceinline__ void ldsm_x4(uint32_t& r0, uint32_t& r1,
                                        uint32_t& r2, uint32_t& r3, uint32_t addr) {
    asm volatile("ldmatrix.sync.aligned.m8n8.x4.shared.b16 {%0,%1,%2,%3}, [%4];"
                 : "=r"(r0), "=r"(r1), "=r"(r2), "=r"(r3) : "r"(addr));
}

__device__ __forceinline__ void mma_bf16(float* d, const uint32_t* a, const uint32_t* b) {
    asm volatile("mma.sync.aligned.m16n8k16.row.col.f32.bf16.bf16.f32 "
                 "{%0,%1,%2,%3}, {%4,%5,%6,%7}, {%8,%9}, {%0,%1,%2,%3};"
                 : "+f"(d[0]), "+f"(d[1]), "+f"(d[2]), "+f"(d[3])
                 : "r"(a[0]), "r"(a[1]), "r"(a[2]), "r"(a[3]), "r"(b[0]), "r"(b[1]));
}

// physical byte offset of 16B chunk (row, chunk) in a [128r x 256B] tile
__device__ __forceinline__ uint32_t sw(int row, int chunk) {
    return (uint32_t)(row * 256 + ((chunk ^ (row & 7)) << 4));
}

// 8 consecutive fp32 -> 8 bf16 hi + 8 bf16 lo (packed as uint4 each)
__device__ __forceinline__ void cvt8(float4 a, float4 b, uint4& hi, uint4& lo) {
    float x[8] = {a.x, a.y, a.z, a.w, b.x, b.y, b.z, b.w};
    uint32_t hu[4], lu[4];
    #pragma unroll
    for (int p = 0; p < 4; p++) {
        __nv_bfloat16 h0 = __float2bfloat16(x[2 * p]);
        __nv_bfloat16 h1 = __float2bfloat16(x[2 * p + 1]);
        __nv_bfloat16 l0 = __float2bfloat16(x[2 * p]     - __bfloat162float(h0));
        __nv_bfloat16 l1 = __float2bfloat16(x[2 * p + 1] - __bfloat162float(h1));
        hu[p] = (uint32_t)__bfloat16_as_ushort(h0) | ((uint32_t)__bfloat16_as_ushort(h1) << 16);
        lu[p] = (uint32_t)__bfloat16_as_ushort(l0) | ((uint32_t)__bfloat16_as_ushort(l1) << 16);
    }
    hi = make_uint4(hu[0], hu[1], hu[2], hu[3]);
    lo = make_uint4(lu[0], lu[1], lu[2], lu[3]);
}

__global__ __launch_bounds__(256) void build_table_kernel(
    const float* __restrict__ E,
    const float* __restrict__ P,
    const float* __restrict__ scale_p)
{
    extern __shared__ char smem_raw[];
    const uint32_t sb0  = smem_u32(smem_raw);
    const uint32_t pad  = ((sb0 + 1023) & ~1023u) - sb0;
    char* sm            = smem_raw + pad;
    const uint32_t sbase = sb0 + pad;

    const int tid = threadIdx.x;
    const int m0  = blockIdx.x * 128;
    const int n0  = blockIdx.y * 128;

    // ---- convert A tile (E rows m0..m0+127) and B tile (P rows n0..n0+127)
    #pragma unroll
    for (int i = 0; i < 8; i++) {
        const int idx = i * 256 + tid;              // 0..2047
        const int row = idx >> 4, chunk = idx & 15;
        const float4* g = (const float4*)(E + (size_t)(m0 + row) * PROJ_DIM + chunk * 8);
        uint4 hi, lo;
        cvt8(__ldg(g), __ldg(g + 1), hi, lo);
        const uint32_t off = sw(row, chunk);
        *(uint4*)(sm + A_HI + off) = hi;
        *(uint4*)(sm + A_LO + off) = lo;
    }
    #pragma unroll
    for (int i = 0; i < 8; i++) {
        const int idx = i * 256 + tid;
        const int row = idx >> 4, chunk = idx & 15;
        const float4* g = (const float4*)(P + (size_t)(n0 + row) * PROJ_DIM + chunk * 8);
        uint4 hi, lo;
        cvt8(__ldg(g), __ldg(g + 1), hi, lo);
        const uint32_t off = sw(row, chunk);
        *(uint4*)(sm + B_HI + off) = hi;
        *(uint4*)(sm + B_LO + off) = lo;
    }
    __syncthreads();

    // ---- mma mainloop: warp w covers rows wm*32..+31, cols wn*64..+63
    const int w    = tid >> 5;
    const int lane = tid & 31;
    const int wm   = w & 3;
    const int wn   = w >> 2;

    float acc[2][8][4];
    #pragma unroll
    for (int mf = 0; mf < 2; mf++)
        #pragma unroll
        for (int nf = 0; nf < 8; nf++)
            #pragma unroll
            for (int q = 0; q < 4; q++) acc[mf][nf][q] = 0.0f;

    // per-lane row components (fixed across k)
    int rowA[2], rowB[4];
    #pragma unroll
    for (int mf = 0; mf < 2; mf++)
        rowA[mf] = wm * 32 + mf * 16 + (lane & 7) + (lane & 8);
    #pragma unroll
    for (int bp = 0; bp < 4; bp++)
        rowB[bp] = wn * 64 + bp * 16 + (lane & 7) + ((lane & 16) >> 1);

    const int ckA = lane >> 4;          // +0/+1 chunk within k16
    const int ckB = (lane >> 3) & 1;

    #pragma unroll
    for (int kk = 0; kk < 8; kk++) {
        uint32_t ah[2][4], al[2][4];
        #pragma unroll
        for (int mf = 0; mf < 2; mf++) {
            const uint32_t off = sw(rowA[mf], 2 * kk + ckA);
            ldsm_x4(ah[mf][0], ah[mf][1], ah[mf][2], ah[mf][3], sbase + A_HI + off);
            ldsm_x4(al[mf][0], al[mf][1], al[mf][2], al[mf][3], sbase + A_LO + off);
        }
        uint32_t bh[8][2], bl[8][2];
        #pragma unroll
        for (int bp = 0; bp < 4; bp++) {
            const uint32_t off = sw(rowB[bp], 2 * kk + ckB);
            ldsm_x4(bh[2 * bp][0], bh[2 * bp][1], bh[2 * bp + 1][0], bh[2 * bp + 1][1],
                    sbase + B_HI + off);
            ldsm_x4(bl[2 * bp][0], bl[2 * bp][1], bl[2 * bp + 1][0], bl[2 * bp + 1][1],
                    sbase + B_LO + off);
        }
        #pragma unroll
        for (int mf = 0; mf < 2; mf++)
            #pragma unroll
            for (int nf = 0; nf < 8; nf++) {
                mma_bf16(acc[mf][nf], ah[mf], bh[nf]);
                mma_bf16(acc[mf][nf], ah[mf], bl[nf]);
                mma_bf16(acc[mf][nf], al[mf], bh[nf]);
            }
    }

    // ---- epilogue: scale + store with .cs (don't pollute L2 ahead of gather)
    const float s = __ldg(scale_p);
    #pragma unroll
    for (int mf = 0; mf < 2; mf++) {
        const int r0 = m0 + wm * 32 + mf * 16 + (lane >> 2);
        #pragma unroll
        for (int nf = 0; nf < 8; nf++) {
            const int c = n0 + wn * 64 + nf * 8 + (lane & 3) * 2;
            float2 v0 = make_float2(acc[mf][nf][0] * s, acc[mf][nf][1] * s);
            float2 v1 = make_float2(acc[mf][nf][2] * s, acc[mf][nf][3] * s);
            __stcs((float2*)&g_fused[(size_t)r0 * MODEL_DIM + c], v0);
            __stcs((float2*)&g_fused[(size_t)(r0 + 8) * MODEL_DIM + c], v1);
        }
    }
}

// ===========================================================================
// Kernel 2: hash + gather + stream out (LTS-bound at ~88% of cap; unchanged).
// ===========================================================================
__device__ __forceinline__ int hash_at(const int* __restrict__ tok, int t) {
    const int s = t & (SEQ - 1);
    if (s == 0) return HASH_SIZE - 1;
    const int t1 = __ldg(tok + t);
    const int t0 = __ldg(tok + t - 1);
    // products < 2^31: no wrap; matches jnp.mod exactly
    return ((36313 * t1) ^ (27191 * t0)) % (HASH_SIZE - 1);
}

__global__ __launch_bounds__(256) void gather_kernel(
    const int* __restrict__ tok,
    float* __restrict__ out)
{
    const int warp = (blockIdx.x * 256 + threadIdx.x) >> 5;
    const int lane = threadIdx.x & 31;
    const int tA = warp * 2, tB = warp * 2 + 1;

    const int hA = hash_at(tok, tA);
    const int hB = hash_at(tok, tB);

    const float4* sA = (const float4*)(g_fused + (size_t)hA * MODEL_DIM);
    const float4* sB = (const float4*)(g_fused + (size_t)hB * MODEL_DIM);
    float4* dA = (float4*)(out + (size_t)tA * MODEL_DIM);
    float4* dB = (float4*)(out + (size_t)tB * MODEL_DIM);

    float4 a0 = __ldg(sA + lane);
    float4 a1 = __ldg(sA + lane + 32);
    float4 a2 = __ldg(sA + lane + 64);
    float4 a3 = __ldg(sA + lane + 96);
    float4 b0 = __ldg(sB + lane);
    float4 b1 = __ldg(sB + lane + 32);
    float4 b2 = __ldg(sB + lane + 64);
    float4 b3 = __ldg(sB + lane + 96);

    __stcs(dA + lane,      a0);
    __stcs(dA + lane + 32, a1);
    __stcs(dA + lane + 64, a2);
    __stcs(dA + lane + 96, a3);
    __stcs(dB + lane,      b0);
    __stcs(dB + lane + 32, b1);
    __stcs(dB + lane + 64, b2);
    __stcs(dB + lane + 96, b3);
}

// ===========================================================================
// Inputs (metadata order): token_ids(i32), embed_weight(f32), proj_weight(f32), scale(f32[1])
// ===========================================================================
extern "C" void kernel_launch(void* const* d_in, const int* in_sizes, int n_in,
                              void* d_out, int out_size)
{
    const int*   tok   = (const int*)d_in[0];
    const float* E     = (const float*)d_in[1];
    const float* P     = (const float*)d_in[2];
    const float* scale = (const float*)d_in[3];
    float*       out   = (float*)d_out;

    cudaFuncSetAttribute(build_table_kernel,
                         cudaFuncAttributeMaxDynamicSharedMemorySize, SMEM_DYN);

    dim3 gemm_grid(HASH_SIZE / 128, MODEL_DIM / 128);   // (80, 4) = 320 CTAs
    build_table_kernel<<<gemm_grid, 256, SMEM_DYN>>>(E, P, scale);

    gather_kernel<<<(NBATCH * SEQ) / 16, 256>>>(tok, out);
}

// round 10
// speedup vs baseline: 1.7807x; 1.1066x over previous
#include <cuda_runtime.h>
#include <cuda_bf16.h>
#include <cstdint>

#define HASH_SIZE 10240
#define PROJ_DIM  128
#define MODEL_DIM 512
#define NBATCH    8
#define SEQ       8192

// Fused table: fused[h][m] = scale * sum_k embed[h][k] * proj[m][k]  (21 MB)
__device__ float g_fused[HASH_SIZE * MODEL_DIM];

// Pre-converted split-bf16 operands, stored in swizzled tile-image layout:
// row-major, 256B per row (16 x 16B chunks), chunk XOR-swizzled by (row&7).
// Any aligned 128/64-row window is a byte-exact smem tile -> linear copy-in.
__device__ __align__(16) unsigned char g_Ehi[HASH_SIZE * 256];
__device__ __align__(16) unsigned char g_Elo[HASH_SIZE * 256];
__device__ __align__(16) unsigned char g_Phi[MODEL_DIM * 256];
__device__ __align__(16) unsigned char g_Plo[MODEL_DIM * 256];

__device__ __forceinline__ uint32_t smem_u32(const void* p) {
    uint32_t a;
    asm("{ .reg .u64 t; cvta.to.shared.u64 t, %1; cvt.u32.u64 %0, t; }" : "=r"(a) : "l"(p));
    return a;
}
__device__ __forceinline__ void ldsm_x4(uint32_t& r0, uint32_t& r1,
                                        uint32_t& r2, uint32_t& r3, uint32_t addr) {
    asm volatile("ldmatrix.sync.aligned.m8n8.x4.shared.b16 {%0,%1,%2,%3}, [%4];"
                 : "=r"(r0), "=r"(r1), "=r"(r2), "=r"(r3) : "r"(addr));
}
__device__ __forceinline__ void mma_bf16(float* d, const uint32_t* a, const uint32_t* b) {
    asm volatile("mma.sync.aligned.m16n8k16.row.col.f32.bf16.bf16.f32 "
                 "{%0,%1,%2,%3}, {%4,%5,%6,%7}, {%8,%9}, {%0,%1,%2,%3};"
                 : "+f"(d[0]), "+f"(d[1]), "+f"(d[2]), "+f"(d[3])
                 : "r"(a[0]), "r"(a[1]), "r"(a[2]), "r"(a[3]), "r"(b[0]), "r"(b[1]));
}
// byte offset of 16B chunk (row, chunk) in the 256B-row swizzled layout
__device__ __forceinline__ uint32_t sw(int row, int chunk) {
    return (uint32_t)(row * 256 + ((chunk ^ (row & 7)) << 4));
}

// ===========================================================================
// Kernel 0: one-shot split-bf16 conversion (bit-ops only).
// hi = truncate-to-bf16 (PRMT pack), lo = rn-bf16(x - hi) (exact residual).
// ===========================================================================
__global__ __launch_bounds__(256) void convert_kernel(
    const float* __restrict__ E,
    const float* __restrict__ P)
{
    int idx = blockIdx.x * 256 + threadIdx.x;
    const int ECH = HASH_SIZE * 16;
    const float* src;
    unsigned char *hid, *lod;
    int row, chunk;
    if (idx < ECH) {
        row = idx >> 4; chunk = idx & 15;
        src = E + (size_t)row * PROJ_DIM + chunk * 8;
        hid = g_Ehi; lod = g_Elo;
    } else {
        idx -= ECH;
        if (idx >= MODEL_DIM * 16) return;
        row = idx >> 4; chunk = idx & 15;
        src = P + (size_t)row * PROJ_DIM + chunk * 8;
        hid = g_Phi; lod = g_Plo;
    }
    float4 a = __ldg((const float4*)src);
    float4 b = __ldg((const float4*)src + 1);
    float x[8] = {a.x, a.y, a.z, a.w, b.x, b.y, b.z, b.w};
    uint32_t h[4], l[4];
    #pragma unroll
    for (int p = 0; p < 4; p++) {
        const uint32_t u0 = __float_as_uint(x[2 * p]);
        const uint32_t u1 = __float_as_uint(x[2 * p + 1]);
        asm("prmt.b32 %0, %1, %2, 0x7632;" : "=r"(h[p]) : "r"(u0), "r"(u1));
        const float r0 = x[2 * p]     - __uint_as_float(u0 & 0xffff0000u);
        const float r1 = x[2 * p + 1] - __uint_as_float(u1 & 0xffff0000u);
        __nv_bfloat162 t = __floats2bfloat162_rn(r0, r1);   // (r0 lo, r1 hi)
        l[p] = *(uint32_t*)&t;
    }
    const uint32_t off = sw(row, chunk);
    *(uint4*)(hid + off) = make_uint4(h[0], h[1], h[2], h[3]);
    *(uint4*)(lod + off) = make_uint4(l[0], l[1], l[2], l[3]);
}

// ===========================================================================
// Kernel 1: GEMM on mma.sync bf16, split-3-product. Pure copy-in + MMA.
// CTA tile M=128, N=64, K=128. 96 KB smem -> 2 CTAs/SM. Grid (80,8)=640.
// ===========================================================================
#define A_HI 0
#define A_LO 32768
#define B_HI 65536
#define B_LO 81920
#define SMEM_DYN (98304 + 1024)

__global__ __launch_bounds__(256) void build_table_kernel(
    const float* __restrict__ scale_p)
{
    extern __shared__ char smem_raw[];
    const uint32_t sb0  = smem_u32(smem_raw);
    const uint32_t pad  = ((sb0 + 1023) & ~1023u) - sb0;
    char* smp           = smem_raw + pad;
    const uint32_t sbase = sb0 + pad;

    const int tid = threadIdx.x;
    const int m0  = blockIdx.x * 128;
    const int n0  = blockIdx.y * 64;

    // ---- copy-in: A hi/lo 32 KB each (2048 uint4), B hi/lo 16 KB (1024)
    {
        const uint4* gAh = (const uint4*)(g_Ehi + (size_t)m0 * 256);
        const uint4* gAl = (const uint4*)(g_Elo + (size_t)m0 * 256);
        #pragma unroll
        for (int i = 0; i < 8; i++) {
            const int t = i * 256 + tid;
            *(uint4*)(smp + A_HI + t * 16) = __ldg(gAh + t);
            *(uint4*)(smp + A_LO + t * 16) = __ldg(gAl + t);
        }
        const uint4* gBh = (const uint4*)(g_Phi + (size_t)n0 * 256);
        const uint4* gBl = (const uint4*)(g_Plo + (size_t)n0 * 256);
        #pragma unroll
        for (int i = 0; i < 4; i++) {
            const int t = i * 256 + tid;
            *(uint4*)(smp + B_HI + t * 16) = __ldg(gBh + t);
            *(uint4*)(smp + B_LO + t * 16) = __ldg(gBl + t);
        }
    }
    __syncthreads();

    // ---- mma mainloop: warp w -> rows wm*32..+31, cols wn*32..+31
    const int w    = tid >> 5;
    const int lane = tid & 31;
    const int wm   = w & 3;
    const int wn   = w >> 2;          // 0..1

    float acc[2][4][4];
    #pragma unroll
    for (int mf = 0; mf < 2; mf++)
        #pragma unroll
        for (int nf = 0; nf < 4; nf++)
            #pragma unroll
            for (int q = 0; q < 4; q++) acc[mf][nf][q] = 0.0f;

    int rowA[2], rowB[2];
    #pragma unroll
    for (int mf = 0; mf < 2; mf++)
        rowA[mf] = wm * 32 + mf * 16 + (lane & 7) + (lane & 8);
    #pragma unroll
    for (int bp = 0; bp < 2; bp++)
        rowB[bp] = wn * 32 + bp * 16 + (lane & 7) + ((lane & 16) >> 1);

    const int ckA = lane >> 4;
    const int ckB = (lane >> 3) & 1;

    #pragma unroll
    for (int kk = 0; kk < 8; kk++) {
        uint32_t ah[2][4], al[2][4];
        #pragma unroll
        for (int mf = 0; mf < 2; mf++) {
            const uint32_t off = sw(rowA[mf], 2 * kk + ckA);
            ldsm_x4(ah[mf][0], ah[mf][1], ah[mf][2], ah[mf][3], sbase + A_HI + off);
            ldsm_x4(al[mf][0], al[mf][1], al[mf][2], al[mf][3], sbase + A_LO + off);
        }
        uint32_t bh[4][2], bl[4][2];
        #pragma unroll
        for (int bp = 0; bp < 2; bp++) {
            const uint32_t off = sw(rowB[bp], 2 * kk + ckB);
            ldsm_x4(bh[2 * bp][0], bh[2 * bp][1], bh[2 * bp + 1][0], bh[2 * bp + 1][1],
                    sbase + B_HI + off);
            ldsm_x4(bl[2 * bp][0], bl[2 * bp][1], bl[2 * bp + 1][0], bl[2 * bp + 1][1],
                    sbase + B_LO + off);
        }
        #pragma unroll
        for (int mf = 0; mf < 2; mf++)
            #pragma unroll
            for (int nf = 0; nf < 4; nf++) {
                mma_bf16(acc[mf][nf], ah[mf], bh[nf]);
                mma_bf16(acc[mf][nf], ah[mf], bl[nf]);
                mma_bf16(acc[mf][nf], al[mf], bh[nf]);
            }
    }

    // ---- epilogue: scale + streaming store
    const float s = __ldg(scale_p);
    #pragma unroll
    for (int mf = 0; mf < 2; mf++) {
        const int r0 = m0 + wm * 32 + mf * 16 + (lane >> 2);
        #pragma unroll
        for (int nf = 0; nf < 4; nf++) {
            const int c = n0 + wn * 32 + nf * 8 + (lane & 3) * 2;
            float2 v0 = make_float2(acc[mf][nf][0] * s, acc[mf][nf][1] * s);
            float2 v1 = make_float2(acc[mf][nf][2] * s, acc[mf][nf][3] * s);
            __stcs((float2*)&g_fused[(size_t)r0 * MODEL_DIM + c], v0);
            __stcs((float2*)&g_fused[(size_t)(r0 + 8) * MODEL_DIM + c], v1);
        }
    }
}

// ===========================================================================
// Kernel 2: hash + gather + stream out (LTS-bound at ~88% of cap; unchanged).
// ===========================================================================
__device__ __forceinline__ int hash_at(const int* __restrict__ tok, int t) {
    const int s = t & (SEQ - 1);
    if (s == 0) return HASH_SIZE - 1;
    const int t1 = __ldg(tok + t);
    const int t0 = __ldg(tok + t - 1);
    // products < 2^31: no wrap; matches jnp.mod exactly
    return ((36313 * t1) ^ (27191 * t0)) % (HASH_SIZE - 1);
}

__global__ __launch_bounds__(256) void gather_kernel(
    const int* __restrict__ tok,
    float* __restrict__ out)
{
    const int warp = (blockIdx.x * 256 + threadIdx.x) >> 5;
    const int lane = threadIdx.x & 31;
    const int tA = warp * 2, tB = warp * 2 + 1;

    const int hA = hash_at(tok, tA);
    const int hB = hash_at(tok, tB);

    const float4* sA = (const float4*)(g_fused + (size_t)hA * MODEL_DIM);
    const float4* sB = (const float4*)(g_fused + (size_t)hB * MODEL_DIM);
    float4* dA = (float4*)(out + (size_t)tA * MODEL_DIM);
    float4* dB = (float4*)(out + (size_t)tB * MODEL_DIM);

    float4 a0 = __ldg(sA + lane);
    float4 a1 = __ldg(sA + lane + 32);
    float4 a2 = __ldg(sA + lane + 64);
    float4 a3 = __ldg(sA + lane + 96);
    float4 b0 = __ldg(sB + lane);
    float4 b1 = __ldg(sB + lane + 32);
    float4 b2 = __ldg(sB + lane + 64);
    float4 b3 = __ldg(sB + lane + 96);

    __stcs(dA + lane,      a0);
    __stcs(dA + lane + 32, a1);
    __stcs(dA + lane + 64, a2);
    __stcs(dA + lane + 96, a3);
    __stcs(dB + lane,      b0);
    __stcs(dB + lane + 32, b1);
    __stcs(dB + lane + 64, b2);
    __stcs(dB + lane + 96, b3);
}

// ===========================================================================
// Inputs (metadata order): token_ids(i32), embed_weight(f32), proj_weight(f32), scale(f32[1])
// ===========================================================================
extern "C" void kernel_launch(void* const* d_in, const int* in_sizes, int n_in,
                              void* d_out, int out_size)
{
    const int*   tok   = (const int*)d_in[0];
    const float* E     = (const float*)d_in[1];
    const float* P     = (const float*)d_in[2];
    const float* scale = (const float*)d_in[3];
    float*       out   = (float*)d_out;

    cudaFuncSetAttribute(build_table_kernel,
                         cudaFuncAttributeMaxDynamicSharedMemorySize, SMEM_DYN);

    const int nconv = (HASH_SIZE + MODEL_DIM) * 16;          // 172032 chunks
    convert_kernel<<<(nconv + 255) / 256, 256>>>(E, P);

    dim3 gemm_grid(HASH_SIZE / 128, MODEL_DIM / 64);         // (80, 8) = 640
    build_table_kernel<<<gemm_grid, 256, SMEM_DYN>>>(scale);

    gather_kernel<<<(NBATCH * SEQ) / 16, 256>>>(tok, out);
}